// round 3
// baseline (speedup 1.0000x reference)
#include <cuda_runtime.h>

// ---------------------------------------------------------------------------
// MultiHeadedAttention_RPR — fp32 baseline
//   B=4, S=1024, H=16, Dk=64, D_MODEL=1024, MAX_REL_POS=1000, VOCAB=2048
// Pipeline:
//   1. gemm_nt (x3): Q/K/V = in @ W^T + b      -> [BH, S, 64] layout
//   2. logits_kernel: QK^T + Q.embK[rel]       -> weights buffer (pre-softmax)
//   3. softmax_kernel: rowwise softmax in place
//   4. av_kernel: W V + W embV[rel]            -> x [B,S,1024]
//   5. gemm_nt: out = x @ Wo^T + bo            -> d_out
// ---------------------------------------------------------------------------

#define N_S    1024
#define N_BH   64
#define N_DK   64
#define OUT_ELEMS   4194304      // 4*1024*1024
#define W_ELEMS     67108864     // 4*16*1024*1024

// static scratch (allocation-free rule: __device__ globals)
__device__ float g_q[OUT_ELEMS];
__device__ float g_k[OUT_ELEMS];
__device__ float g_v[OUT_ELEMS];
__device__ float g_x[OUT_ELEMS];
__device__ float g_w[W_ELEMS];   // fallback weights scratch if not part of d_out

// ---------------------------------------------------------------------------
// Generic C = A @ B^T + bias ; A[M,K], B[N,K], fp32.
// mode 0: C[m*N+n]           (row-major [M,N])
// mode 1: scatter to [B,H,S,Dk]: m=(b,s), n=(h,d) -> ((b*16+h)*1024+s)*64+d
// 64x64 block tile, BK=16, 256 threads, 4x4 per thread.
// ---------------------------------------------------------------------------
__global__ __launch_bounds__(256) void gemm_nt(
    const float* __restrict__ A, const float* __restrict__ Bm,
    const float* __restrict__ bias, float* __restrict__ C,
    int M, int N, int K, int mode)
{
    __shared__ float As[16 * 68];
    __shared__ float Bs[16 * 68];
    const int t  = threadIdx.x;
    const int m0 = blockIdx.y << 6;
    const int n0 = blockIdx.x << 6;
    const int ti = t >> 4, tj = t & 15;
    const int lr = t >> 2;            // 0..63
    const int lc = (t & 3) << 2;      // 0,4,8,12

    const float* Ap = A  + (size_t)(m0 + lr) * K + lc;
    const float* Bp = Bm + (size_t)(n0 + lr) * K + lc;

    float acc[4][4] = {};

    for (int k0 = 0; k0 < K; k0 += 16) {
        float4 av = *(const float4*)(Ap + k0);
        float4 bv = *(const float4*)(Bp + k0);
        __syncthreads();
        As[(lc + 0) * 68 + lr] = av.x; As[(lc + 1) * 68 + lr] = av.y;
        As[(lc + 2) * 68 + lr] = av.z; As[(lc + 3) * 68 + lr] = av.w;
        Bs[(lc + 0) * 68 + lr] = bv.x; Bs[(lc + 1) * 68 + lr] = bv.y;
        Bs[(lc + 2) * 68 + lr] = bv.z; Bs[(lc + 3) * 68 + lr] = bv.w;
        __syncthreads();
        #pragma unroll
        for (int kk = 0; kk < 16; kk++) {
            float4 a = *(const float4*)(As + kk * 68 + (ti << 2));
            float4 b = *(const float4*)(Bs + kk * 68 + (tj << 2));
            float a4[4] = {a.x, a.y, a.z, a.w};
            float b4[4] = {b.x, b.y, b.z, b.w};
            #pragma unroll
            for (int i = 0; i < 4; i++)
                #pragma unroll
                for (int j = 0; j < 4; j++)
                    acc[i][j] += a4[i] * b4[j];
        }
    }

    float4 bb = *(const float4*)(bias + n0 + (tj << 2));
    #pragma unroll
    for (int di = 0; di < 4; di++) {
        int m = m0 + (ti << 2) + di;
        float4 r = make_float4(acc[di][0] + bb.x, acc[di][1] + bb.y,
                               acc[di][2] + bb.z, acc[di][3] + bb.w);
        if (mode == 0) {
            *(float4*)(C + (size_t)m * N + n0 + (tj << 2)) = r;
        } else {
            int b = m >> 10, s = m & 1023;
            int h = n0 >> 6;                       // n-tile == one head (64 cols)
            size_t idx = ((size_t)((b * 16 + h) * 1024 + s)) * 64 + (tj << 2);
            *(float4*)(C + idx) = r;
        }
    }
}

// ---------------------------------------------------------------------------
// Logits: W[bh,q,k] = sum_d Q[bh,q,d] * (K[bh,k,d] + embK[clamp(k-q+1000),d])
// Block: (q-tile of 64) x (bh). Per k-tile of 64: stage K^T, E^T (127 rel rows).
// Thread (ti,tj) computes 4x4 micro-tile; e index = (j-i)+63.
// ---------------------------------------------------------------------------
__global__ __launch_bounds__(256) void logits_kernel(
    const float* __restrict__ Q, const float* __restrict__ K,
    const float* __restrict__ embK, float* __restrict__ W)
{
    extern __shared__ float sm[];
    float* Qt = sm;                 // [64 d][68 i]
    float* Kt = sm + 64 * 68;       // [64 d][68 j]
    float* Et = sm + 2 * 64 * 68;   // [64 d][132 u], u = (j-i)+63 in [0,126]

    const int t  = threadIdx.x;
    const int q0 = blockIdx.x << 6;
    const int bh = blockIdx.y;
    const int ti = t >> 4, tj = t & 15;
    const int cb = ((tj - ti) << 2) + 60;   // base col for the 8 e-values, >= 0

    {   // load Q tile transposed (once)
        const float* Qb = Q + ((size_t)bh * N_S + q0) * N_DK;
        for (int v = t; v < 1024; v += 256) {
            int row = v >> 4, dc = (v & 15) << 2;
            float4 x = *(const float4*)(Qb + row * 64 + dc);
            Qt[(dc + 0) * 68 + row] = x.x; Qt[(dc + 1) * 68 + row] = x.y;
            Qt[(dc + 2) * 68 + row] = x.z; Qt[(dc + 3) * 68 + row] = x.w;
        }
    }

    for (int kt = 0; kt < 16; kt++) {
        const int k0 = kt << 6;
        __syncthreads();
        {   // K tile transposed
            const float* Kb = K + ((size_t)bh * N_S + k0) * N_DK;
            for (int v = t; v < 1024; v += 256) {
                int row = v >> 4, dc = (v & 15) << 2;
                float4 x = *(const float4*)(Kb + row * 64 + dc);
                Kt[(dc + 0) * 68 + row] = x.x; Kt[(dc + 1) * 68 + row] = x.y;
                Kt[(dc + 2) * 68 + row] = x.z; Kt[(dc + 3) * 68 + row] = x.w;
            }
        }
        {   // 127 relative-embedding rows, transposed; clamp handles rel-pos clip
            const int rb = k0 - q0 + 1000 - 63;
            for (int v = t; v < 2032; v += 256) {   // 127*16 float4s
                int u = v >> 4, dc = (v & 15) << 2;
                int r = rb + u; r = r < 0 ? 0 : (r > 2000 ? 2000 : r);
                float4 x = *(const float4*)(embK + (size_t)r * 64 + dc);
                Et[(dc + 0) * 132 + u] = x.x; Et[(dc + 1) * 132 + u] = x.y;
                Et[(dc + 2) * 132 + u] = x.z; Et[(dc + 3) * 132 + u] = x.w;
            }
        }
        __syncthreads();

        float acc[4][4] = {};
        #pragma unroll 8
        for (int d = 0; d < 64; d++) {
            float4 a  = *(const float4*)(Qt + d * 68 + (ti << 2));
            float4 b  = *(const float4*)(Kt + d * 68 + (tj << 2));
            float4 e0 = *(const float4*)(Et + d * 132 + cb);
            float4 e1 = *(const float4*)(Et + d * 132 + cb + 4);
            float a4[4] = {a.x, a.y, a.z, a.w};
            float b4[4] = {b.x, b.y, b.z, b.w};
            float ea[8] = {e0.x, e0.y, e0.z, e0.w, e1.x, e1.y, e1.z, e1.w};
            #pragma unroll
            for (int di = 0; di < 4; di++)
                #pragma unroll
                for (int dj = 0; dj < 4; dj++)
                    acc[di][dj] += a4[di] * (b4[dj] + ea[dj - di + 3]);
        }

        #pragma unroll
        for (int di = 0; di < 4; di++) {
            int qg = q0 + (ti << 2) + di;
            float4 r4 = make_float4(acc[di][0], acc[di][1], acc[di][2], acc[di][3]);
            *(float4*)(W + ((size_t)bh * N_S + qg) * N_S + k0 + (tj << 2)) = r4;
        }
    }
}

// ---------------------------------------------------------------------------
// Row softmax in place over [65536 rows x 1024]
// ---------------------------------------------------------------------------
__global__ __launch_bounds__(256) void softmax_kernel(float* __restrict__ W)
{
    __shared__ float red[8];
    float* p = W + (size_t)blockIdx.x * 1024;
    const int t = threadIdx.x;
    float4 v = ((float4*)p)[t];

    float m = fmaxf(fmaxf(v.x, v.y), fmaxf(v.z, v.w));
    #pragma unroll
    for (int o = 16; o; o >>= 1) m = fmaxf(m, __shfl_xor_sync(0xffffffffu, m, o));
    if ((t & 31) == 0) red[t >> 5] = m;
    __syncthreads();
    m = fmaxf(fmaxf(fmaxf(red[0], red[1]), fmaxf(red[2], red[3])),
              fmaxf(fmaxf(red[4], red[5]), fmaxf(red[6], red[7])));

    float e0 = __expf(v.x - m), e1 = __expf(v.y - m);
    float e2 = __expf(v.z - m), e3 = __expf(v.w - m);
    float s = (e0 + e1) + (e2 + e3);
    #pragma unroll
    for (int o = 16; o; o >>= 1) s += __shfl_xor_sync(0xffffffffu, s, o);
    __syncthreads();
    if ((t & 31) == 0) red[t >> 5] = s;
    __syncthreads();
    s = ((red[0] + red[1]) + (red[2] + red[3])) + ((red[4] + red[5]) + (red[6] + red[7]));
    float inv = 1.0f / s;
    ((float4*)p)[t] = make_float4(e0 * inv, e1 * inv, e2 * inv, e3 * inv);
}

// ---------------------------------------------------------------------------
// x[bh,q,d] = sum_k W[bh,q,k] * (V[bh,k,d] + embV[clamp(k-q+1000),d])
// output written directly in [B, S, H*64] layout for the final projection.
// Thread owns (row i, 16 d's).
// ---------------------------------------------------------------------------
__global__ __launch_bounds__(256) void av_kernel(
    const float* __restrict__ W, const float* __restrict__ V,
    const float* __restrict__ embV, float* __restrict__ X)
{
    extern __shared__ float sm[];
    float* Ws = sm;                 // [64 i][68 j]
    float* Vs = sm + 64 * 68;       // [64 j][68 d]
    float* Es = sm + 2 * 64 * 68;   // [127 u][68 d]

    const int t  = threadIdx.x;
    const int q0 = blockIdx.x << 6;
    const int bh = blockIdx.y;
    const int i  = t >> 2;
    const int d0 = (t & 3) << 4;

    float acc[16] = {};

    for (int kt = 0; kt < 16; kt++) {
        const int k0 = kt << 6;
        __syncthreads();
        for (int v = t; v < 1024; v += 256) {
            int row = v >> 4, c = (v & 15) << 2;
            *(float4*)(Ws + row * 68 + c) =
                *(const float4*)(W + ((size_t)bh * N_S + q0 + row) * N_S + k0 + c);
            *(float4*)(Vs + row * 68 + c) =
                *(const float4*)(V + ((size_t)bh * N_S + k0 + row) * N_DK + c);
        }
        {
            const int rb = k0 - q0 + 1000 - 63;
            for (int v = t; v < 2032; v += 256) {
                int u = v >> 4, c = (v & 15) << 2;
                int r = rb + u; r = r < 0 ? 0 : (r > 2000 ? 2000 : r);
                *(float4*)(Es + u * 68 + c) = *(const float4*)(embV + (size_t)r * 64 + c);
            }
        }
        __syncthreads();

        #pragma unroll 4
        for (int j = 0; j < 64; j++) {
            float w = Ws[i * 68 + j];
            const float* vp = Vs + j * 68 + d0;
            const float* ep = Es + (j - i + 63) * 68 + d0;
            #pragma unroll
            for (int c = 0; c < 4; c++) {
                float4 v4 = *(const float4*)(vp + (c << 2));
                float4 e4 = *(const float4*)(ep + (c << 2));
                acc[c * 4 + 0] += w * (v4.x + e4.x);
                acc[c * 4 + 1] += w * (v4.y + e4.y);
                acc[c * 4 + 2] += w * (v4.z + e4.z);
                acc[c * 4 + 3] += w * (v4.w + e4.w);
            }
        }
    }

    const int b = bh >> 4, h = bh & 15;
    float* xp = X + ((size_t)(b * N_S + q0 + i)) * 1024 + h * 64 + d0;
    #pragma unroll
    for (int c = 0; c < 4; c++)
        *(float4*)(xp + (c << 2)) = make_float4(acc[c * 4 + 0], acc[c * 4 + 1],
                                                acc[c * 4 + 2], acc[c * 4 + 3]);
}

// ---------------------------------------------------------------------------
extern "C" void kernel_launch(void* const* d_in, const int* in_sizes, int n_in,
                              void* d_out, int out_size)
{
    const float* query = (const float*)d_in[0];
    const float* key   = (const float*)d_in[1];
    const float* value = (const float*)d_in[2];
    const float* Wq    = (const float*)d_in[3];
    const float* bq    = (const float*)d_in[4];
    const float* Wk    = (const float*)d_in[5];
    const float* bk    = (const float*)d_in[6];
    const float* Wv    = (const float*)d_in[7];
    const float* bv    = (const float*)d_in[8];
    const float* Wo    = (const float*)d_in[9];
    const float* bo    = (const float*)d_in[10];
    const float* embK  = (const float*)d_in[11];
    const float* embV  = (const float*)d_in[12];
    (void)in_sizes; (void)n_in;

    float *qp, *kp, *vp, *xp, *wscr;
    cudaGetSymbolAddress((void**)&qp,  g_q);
    cudaGetSymbolAddress((void**)&kp,  g_k);
    cudaGetSymbolAddress((void**)&vp,  g_v);
    cudaGetSymbolAddress((void**)&xp,  g_x);
    cudaGetSymbolAddress((void**)&wscr, g_w);

    float* out     = (float*)d_out;
    float* outPtr  = out;
    float* weights;
    if ((long long)out_size >= (long long)OUT_ELEMS + (long long)W_ELEMS) {
        weights = out + OUT_ELEMS;                 // (out, weights) concatenated
    } else if (out_size == W_ELEMS) {
        weights = out;                              // weights-only output
        outPtr  = qp;                               // park projected out in scratch
    } else {
        weights = wscr;                             // out-only output
    }

    const int smem_logits = (2 * 64 * 68 + 64 * 132) * 4;   // 68608 B
    const int smem_av     = (2 * 64 * 68 + 127 * 68) * 4;   // 69360 B
    cudaFuncSetAttribute(logits_kernel, cudaFuncAttributeMaxDynamicSharedMemorySize, smem_logits);
    cudaFuncSetAttribute(av_kernel,     cudaFuncAttributeMaxDynamicSharedMemorySize, smem_av);

    dim3 blk(256);
    dim3 gproj(16, 64);     // N=1024 -> 16 n-tiles, M=4096 -> 64 m-tiles
    dim3 gatt(16, 64);      // 16 q-tiles x 64 (b,h)

    // 1. projections, scattered directly into [BH, S, 64]
    gemm_nt<<<gproj, blk>>>(query, Wq, bq, qp, 4096, 1024, 1024, 1);
    gemm_nt<<<gproj, blk>>>(key,   Wk, bk, kp, 4096, 1024, 1024, 1);
    gemm_nt<<<gproj, blk>>>(value, Wv, bv, vp, 4096, 1024, 1024, 1);

    // 2. fused content + relative-position logits
    logits_kernel<<<gatt, blk, smem_logits>>>(qp, kp, embK, weights);

    // 3. softmax (in place; this IS the `weights` output)
    softmax_kernel<<<65536, blk>>>(weights);

    // 4. fused W·V + W·embV, output in [B,S,1024]
    av_kernel<<<gatt, blk, smem_av>>>(weights, vp, embV, xp);

    // 5. output projection
    gemm_nt<<<gproj, blk>>>(xp, Wo, bo, outPtr, 4096, 1024, 1024, 0);
}

// round 4
// speedup vs baseline: 1.7928x; 1.7928x over previous
#include <cuda_runtime.h>

// ---------------------------------------------------------------------------
// MultiHeadedAttention_RPR — optimized fp32 (LDS-balanced 8x8 micro-tiles)
//   B=4, S=1024, H=16, Dk=64, D_MODEL=1024, MAX_REL_POS=1000, VOCAB=2048
// ---------------------------------------------------------------------------

#define N_S    1024
#define OUT_ELEMS   4194304      // 4*1024*1024
#define W_ELEMS     67108864     // 4*16*1024*1024

__device__ float g_q[OUT_ELEMS];
__device__ float g_k[OUT_ELEMS];
__device__ float g_v[OUT_ELEMS];
__device__ float g_x[OUT_ELEMS];
__device__ float g_w[W_ELEMS];   // fallback weights scratch

// ---------------------------------------------------------------------------
// C = A @ B^T + bias ; A[M,K], B[N,K], fp32. 128x128 tile, BK=16, 8x8 micro.
// mode 0: C row-major [M,N];  mode 1: scatter to [B,H,S,Dk]
// Double-buffered smem, one __syncthreads per stage.
// ---------------------------------------------------------------------------
__global__ __launch_bounds__(256) void gemm_nt(
    const float* __restrict__ A, const float* __restrict__ Bm,
    const float* __restrict__ bias, float* __restrict__ C,
    int M, int N, int K, int mode)
{
    __shared__ float As[2][16][132];
    __shared__ float Bs[2][16][132];
    const int t  = threadIdx.x;
    const int m0 = blockIdx.y << 7;
    const int n0 = blockIdx.x << 7;
    const int ti = t >> 4, tj = t & 15;
    const int i0 = ti << 3, j0 = tj << 3;

    // loader: 128x16 tile = 512 float4; thread loads rows r0 and r0+64
    const int r0 = t >> 2;              // 0..63
    const int c0 = (t & 3) << 2;        // 0,4,8,12
    const float* Ap = A  + (size_t)(m0 + r0) * K + c0;
    const float* Bp = Bm + (size_t)(n0 + r0) * K + c0;
    const size_t half = (size_t)64 * K;

    float4 a0 = *(const float4*)(Ap);
    float4 a1 = *(const float4*)(Ap + half);
    float4 b0 = *(const float4*)(Bp);
    float4 b1 = *(const float4*)(Bp + half);

    float acc[8][8] = {};
    const int S = K >> 4;

    for (int s = 0; s < S; s++) {
        const int p = s & 1;
        As[p][c0+0][r0] = a0.x; As[p][c0+1][r0] = a0.y;
        As[p][c0+2][r0] = a0.z; As[p][c0+3][r0] = a0.w;
        As[p][c0+0][r0+64] = a1.x; As[p][c0+1][r0+64] = a1.y;
        As[p][c0+2][r0+64] = a1.z; As[p][c0+3][r0+64] = a1.w;
        Bs[p][c0+0][r0] = b0.x; Bs[p][c0+1][r0] = b0.y;
        Bs[p][c0+2][r0] = b0.z; Bs[p][c0+3][r0] = b0.w;
        Bs[p][c0+0][r0+64] = b1.x; Bs[p][c0+1][r0+64] = b1.y;
        Bs[p][c0+2][r0+64] = b1.z; Bs[p][c0+3][r0+64] = b1.w;
        __syncthreads();

        if (s + 1 < S) {
            const float* Ap2 = Ap + (size_t)(s + 1) * 16;
            const float* Bp2 = Bp + (size_t)(s + 1) * 16;
            a0 = *(const float4*)(Ap2);
            a1 = *(const float4*)(Ap2 + half);
            b0 = *(const float4*)(Bp2);
            b1 = *(const float4*)(Bp2 + half);
        }

        #pragma unroll
        for (int kk = 0; kk < 16; kk++) {
            float4 xA = *(const float4*)(&As[p][kk][i0]);
            float4 xB = *(const float4*)(&As[p][kk][i0 + 4]);
            float4 yA = *(const float4*)(&Bs[p][kk][j0]);
            float4 yB = *(const float4*)(&Bs[p][kk][j0 + 4]);
            float a8[8] = {xA.x, xA.y, xA.z, xA.w, xB.x, xB.y, xB.z, xB.w};
            float b8[8] = {yA.x, yA.y, yA.z, yA.w, yB.x, yB.y, yB.z, yB.w};
            #pragma unroll
            for (int r = 0; r < 8; r++)
                #pragma unroll
                for (int c = 0; c < 8; c++)
                    acc[r][c] += a8[r] * b8[c];
        }
        // single sync per stage is sufficient: next store targets the other buffer,
        // guarded by this stage's sync (all compute(s-1) done before it).
    }

    float4 bbA = *(const float4*)(bias + n0 + j0);
    float4 bbB = *(const float4*)(bias + n0 + j0 + 4);
    float bb[8] = {bbA.x, bbA.y, bbA.z, bbA.w, bbB.x, bbB.y, bbB.z, bbB.w};

    #pragma unroll
    for (int r = 0; r < 8; r++) {
        const int m = m0 + i0 + r;
        float4 oA = make_float4(acc[r][0]+bb[0], acc[r][1]+bb[1], acc[r][2]+bb[2], acc[r][3]+bb[3]);
        float4 oB = make_float4(acc[r][4]+bb[4], acc[r][5]+bb[5], acc[r][6]+bb[6], acc[r][7]+bb[7]);
        if (mode == 0) {
            float* p = C + (size_t)m * N + n0 + j0;
            *(float4*)(p) = oA; *(float4*)(p + 4) = oB;
        } else {
            const int b = m >> 10, sI = m & 1023;
            const int n = n0 + j0;
            const int h = n >> 6, d = n & 63;
            float* p = C + ((size_t)((b * 16 + h) * 1024 + sI)) * 64 + d;
            *(float4*)(p) = oA; *(float4*)(p + 4) = oB;
        }
    }
}

// ---------------------------------------------------------------------------
// Logits: W[bh,q,k] = sum_d Q[bh,q,d] * (K[bh,k,d] + embK[clamp(k-q+1000),d])
// 128(q) x 128(k) tiles, 8x8 micro. d-major smem; 127..255-row rel-emb band.
// ---------------------------------------------------------------------------
__global__ __launch_bounds__(256) void logits_kernel(
    const float* __restrict__ Q, const float* __restrict__ K,
    const float* __restrict__ embK, float* __restrict__ W)
{
    extern __shared__ float sm[];
    float* Qt = sm;                  // [64 d][132]
    float* Kt = sm + 64 * 132;       // [64 d][132]
    float* Et = sm + 2 * 64 * 132;   // [64 d][260], u = j-i+127 in [0,254]

    const int t  = threadIdx.x;
    const int q0 = blockIdx.x << 7;
    const int bh = blockIdx.y;
    const int ti = t >> 4, tj = t & 15;
    const int i0 = ti << 3, j0 = tj << 3;
    const int ub = ((tj - ti) << 3) + 120;   // e-window base (>=0, f4-aligned)

    {   // Q tile transposed, once
        const float* Qb = Q + ((size_t)bh * N_S + q0) * 64;
        for (int v = t; v < 2048; v += 256) {
            int row = v >> 4, dc = (v & 15) << 2;
            float4 x = *(const float4*)(Qb + row * 64 + dc);
            Qt[(dc + 0) * 132 + row] = x.x; Qt[(dc + 1) * 132 + row] = x.y;
            Qt[(dc + 2) * 132 + row] = x.z; Qt[(dc + 3) * 132 + row] = x.w;
        }
    }

    for (int kt = 0; kt < 8; kt++) {
        const int k0 = kt << 7;
        __syncthreads();
        {   // K tile transposed
            const float* Kb = K + ((size_t)bh * N_S + k0) * 64;
            for (int v = t; v < 2048; v += 256) {
                int row = v >> 4, dc = (v & 15) << 2;
                float4 x = *(const float4*)(Kb + row * 64 + dc);
                Kt[(dc + 0) * 132 + row] = x.x; Kt[(dc + 1) * 132 + row] = x.y;
                Kt[(dc + 2) * 132 + row] = x.z; Kt[(dc + 3) * 132 + row] = x.w;
            }
        }
        {   // 255 relative-embedding rows, transposed (clamped index)
            const int rb = k0 - q0 + 1000 - 127;
            for (int v = t; v < 4080; v += 256) {   // 255*16 float4
                int u = v >> 4, dc = (v & 15) << 2;
                int r = rb + u; r = r < 0 ? 0 : (r > 2000 ? 2000 : r);
                float4 x = *(const float4*)(embK + (size_t)r * 64 + dc);
                Et[(dc + 0) * 260 + u] = x.x; Et[(dc + 1) * 260 + u] = x.y;
                Et[(dc + 2) * 260 + u] = x.z; Et[(dc + 3) * 260 + u] = x.w;
            }
        }
        __syncthreads();

        float acc[8][8] = {};
        #pragma unroll 2
        for (int d = 0; d < 64; d++) {
            float4 xA = *(const float4*)(Qt + d * 132 + i0);
            float4 xB = *(const float4*)(Qt + d * 132 + i0 + 4);
            float4 yA = *(const float4*)(Kt + d * 132 + j0);
            float4 yB = *(const float4*)(Kt + d * 132 + j0 + 4);
            float4 e0 = *(const float4*)(Et + d * 260 + ub);
            float4 e1 = *(const float4*)(Et + d * 260 + ub + 4);
            float4 e2 = *(const float4*)(Et + d * 260 + ub + 8);
            float4 e3 = *(const float4*)(Et + d * 260 + ub + 12);
            float a8[8] = {xA.x, xA.y, xA.z, xA.w, xB.x, xB.y, xB.z, xB.w};
            float b8[8] = {yA.x, yA.y, yA.z, yA.w, yB.x, yB.y, yB.z, yB.w};
            float ee[16] = {e0.x, e0.y, e0.z, e0.w, e1.x, e1.y, e1.z, e1.w,
                            e2.x, e2.y, e2.z, e2.w, e3.x, e3.y, e3.z, e3.w};
            #pragma unroll
            for (int r = 0; r < 8; r++)
                #pragma unroll
                for (int c = 0; c < 8; c++)
                    acc[r][c] += a8[r] * (b8[c] + ee[7 + c - r]);
        }

        float* Wb = W + ((size_t)bh * N_S + q0 + i0) * N_S + k0 + j0;
        #pragma unroll
        for (int r = 0; r < 8; r++) {
            *(float4*)(Wb + (size_t)r * N_S) =
                make_float4(acc[r][0], acc[r][1], acc[r][2], acc[r][3]);
            *(float4*)(Wb + (size_t)r * N_S + 4) =
                make_float4(acc[r][4], acc[r][5], acc[r][6], acc[r][7]);
        }
    }
}

// ---------------------------------------------------------------------------
// Row softmax in place over [65536 rows x 1024]
// ---------------------------------------------------------------------------
__global__ __launch_bounds__(256) void softmax_kernel(float* __restrict__ W)
{
    __shared__ float red[8];
    float* p = W + (size_t)blockIdx.x * 1024;
    const int t = threadIdx.x;
    float4 v = ((float4*)p)[t];

    float m = fmaxf(fmaxf(v.x, v.y), fmaxf(v.z, v.w));
    #pragma unroll
    for (int o = 16; o; o >>= 1) m = fmaxf(m, __shfl_xor_sync(0xffffffffu, m, o));
    if ((t & 31) == 0) red[t >> 5] = m;
    __syncthreads();
    m = fmaxf(fmaxf(fmaxf(red[0], red[1]), fmaxf(red[2], red[3])),
              fmaxf(fmaxf(red[4], red[5]), fmaxf(red[6], red[7])));

    float e0 = __expf(v.x - m), e1 = __expf(v.y - m);
    float e2 = __expf(v.z - m), e3 = __expf(v.w - m);
    float s = (e0 + e1) + (e2 + e3);
    #pragma unroll
    for (int o = 16; o; o >>= 1) s += __shfl_xor_sync(0xffffffffu, s, o);
    __syncthreads();
    if ((t & 31) == 0) red[t >> 5] = s;
    __syncthreads();
    s = ((red[0] + red[1]) + (red[2] + red[3])) + ((red[4] + red[5]) + (red[6] + red[7]));
    float inv = 1.0f / s;
    ((float4*)p)[t] = make_float4(e0 * inv, e1 * inv, e2 * inv, e3 * inv);
}

// ---------------------------------------------------------------------------
// x[bh,q,d] = sum_k W[bh,q,k] * (V[bh,k,d] + embV[clamp(k-q+1000),d])
// 128(q) x 64(d-full) tile; thread = 8 consecutive q-rows x 4 d.
// embV rows via 8-deep register sliding window (1 new f4 per j).
// ---------------------------------------------------------------------------
__global__ __launch_bounds__(256) void av_kernel(
    const float* __restrict__ W, const float* __restrict__ V,
    const float* __restrict__ embV, float* __restrict__ X)
{
    extern __shared__ float sm[];
    float* Ws = sm;                       // [128 i][68 j]
    float* Vs = sm + 128 * 68;            // [64 j][68 d]
    float* Es = sm + (128 + 64) * 68;     // [191 u][68 d]

    const int t  = threadIdx.x;
    const int q0 = blockIdx.x << 7;
    const int bh = blockIdx.y;
    const int tq = t >> 4, td = t & 15;
    const int i0 = tq << 3;      // 0..120
    const int d0 = td << 2;      // 0..60

    float acc[8][4] = {};

    for (int kt = 0; kt < 16; kt++) {
        const int k0 = kt << 6;
        __syncthreads();
        for (int v = t; v < 2048; v += 256) {          // Ws: 128x64
            int row = v >> 4, c = (v & 15) << 2;
            *(float4*)(Ws + row * 68 + c) =
                *(const float4*)(W + ((size_t)bh * N_S + q0 + row) * N_S + k0 + c);
        }
        for (int v = t; v < 1024; v += 256) {          // Vs: 64x64
            int row = v >> 4, c = (v & 15) << 2;
            *(float4*)(Vs + row * 68 + c) =
                *(const float4*)(V + ((size_t)bh * N_S + k0 + row) * 64 + c);
        }
        {                                               // Es: 191 rows
            const int rb = k0 - q0 + 1000 - 127;
            for (int v = t; v < 3056; v += 256) {      // 191*16 f4
                int u = v >> 4, c = (v & 15) << 2;
                int r = rb + u; r = r < 0 ? 0 : (r > 2000 ? 2000 : r);
                *(float4*)(Es + u * 68 + c) = *(const float4*)(embV + (size_t)r * 64 + c);
            }
        }
        __syncthreads();

        // preload ring: slots 0..6 hold u = 120-i0 .. 126-i0  (slot = u & 7)
        float4 ring[8];
        #pragma unroll
        for (int k = 0; k < 7; k++)
            ring[k] = *(const float4*)(Es + (120 - i0 + k) * 68 + d0);

        #pragma unroll 1
        for (int jj = 0; jj < 64; jj += 8) {
            float wl[8][4];
            #pragma unroll
            for (int r = 0; r < 8; r++) {
                float4 x = *(const float4*)(Ws + (i0 + r) * 68 + jj);
                wl[r][0] = x.x; wl[r][1] = x.y; wl[r][2] = x.z; wl[r][3] = x.w;
            }
            #pragma unroll
            for (int js = 0; js < 4; js++) {
                const int j = jj + js;
                ring[(js + 7) & 7] = *(const float4*)(Es + (j + 127 - i0) * 68 + d0);
                float4 v4 = *(const float4*)(Vs + j * 68 + d0);
                #pragma unroll
                for (int r = 0; r < 8; r++) {
                    const float w = wl[r][js];
                    const float4 e4 = ring[(js + 7 - r) & 7];
                    acc[r][0] += w * (v4.x + e4.x);
                    acc[r][1] += w * (v4.y + e4.y);
                    acc[r][2] += w * (v4.z + e4.z);
                    acc[r][3] += w * (v4.w + e4.w);
                }
            }
            #pragma unroll
            for (int r = 0; r < 8; r++) {
                float4 x = *(const float4*)(Ws + (i0 + r) * 68 + jj + 4);
                wl[r][0] = x.x; wl[r][1] = x.y; wl[r][2] = x.z; wl[r][3] = x.w;
            }
            #pragma unroll
            for (int js = 4; js < 8; js++) {
                const int j = jj + js;
                ring[(js + 7) & 7] = *(const float4*)(Es + (j + 127 - i0) * 68 + d0);
                float4 v4 = *(const float4*)(Vs + j * 68 + d0);
                #pragma unroll
                for (int r = 0; r < 8; r++) {
                    const float w = wl[r][js - 4];
                    const float4 e4 = ring[(js + 7 - r) & 7];
                    acc[r][0] += w * (v4.x + e4.x);
                    acc[r][1] += w * (v4.y + e4.y);
                    acc[r][2] += w * (v4.z + e4.z);
                    acc[r][3] += w * (v4.w + e4.w);
                }
            }
        }
    }

    const int b = bh >> 4, h = bh & 15;
    #pragma unroll
    for (int r = 0; r < 8; r++) {
        float* xp = X + ((size_t)(b * N_S + q0 + i0 + r)) * 1024 + h * 64 + d0;
        *(float4*)(xp) = make_float4(acc[r][0], acc[r][1], acc[r][2], acc[r][3]);
    }
}

// ---------------------------------------------------------------------------
extern "C" void kernel_launch(void* const* d_in, const int* in_sizes, int n_in,
                              void* d_out, int out_size)
{
    const float* query = (const float*)d_in[0];
    const float* key   = (const float*)d_in[1];
    const float* value = (const float*)d_in[2];
    const float* Wq    = (const float*)d_in[3];
    const float* bq    = (const float*)d_in[4];
    const float* Wk    = (const float*)d_in[5];
    const float* bk    = (const float*)d_in[6];
    const float* Wv    = (const float*)d_in[7];
    const float* bv    = (const float*)d_in[8];
    const float* Wo    = (const float*)d_in[9];
    const float* bo    = (const float*)d_in[10];
    const float* embK  = (const float*)d_in[11];
    const float* embV  = (const float*)d_in[12];
    (void)in_sizes; (void)n_in;

    float *qp, *kp, *vp, *xp, *wscr;
    cudaGetSymbolAddress((void**)&qp,   g_q);
    cudaGetSymbolAddress((void**)&kp,   g_k);
    cudaGetSymbolAddress((void**)&vp,   g_v);
    cudaGetSymbolAddress((void**)&xp,   g_x);
    cudaGetSymbolAddress((void**)&wscr, g_w);

    float* out    = (float*)d_out;
    float* outPtr = out;
    float* weights;
    if ((long long)out_size >= (long long)OUT_ELEMS + (long long)W_ELEMS) {
        weights = out + OUT_ELEMS;
    } else if (out_size == W_ELEMS) {
        weights = out;
        outPtr  = qp;
    } else {
        weights = wscr;
    }

    const int smem_logits = (2 * 64 * 132 + 64 * 260) * 4;   // 134144 B
    const int smem_av     = ((128 + 64 + 191) * 68) * 4;     // 104176 B
    static int configured = 0;
    if (!configured) {
        cudaFuncSetAttribute(logits_kernel, cudaFuncAttributeMaxDynamicSharedMemorySize, smem_logits);
        cudaFuncSetAttribute(av_kernel,     cudaFuncAttributeMaxDynamicSharedMemorySize, smem_av);
        configured = 1;
    }

    dim3 blk(256);
    dim3 gproj(8, 32);      // N=1024 -> 8 n-tiles of 128, M=4096 -> 32 m-tiles of 128
    dim3 gatt(8, 64);       // 8 q-tiles of 128 x 64 (b,h)

    gemm_nt<<<gproj, blk>>>(query, Wq, bq, qp, 4096, 1024, 1024, 1);
    gemm_nt<<<gproj, blk>>>(key,   Wk, bk, kp, 4096, 1024, 1024, 1);
    gemm_nt<<<gproj, blk>>>(value, Wv, bv, vp, 4096, 1024, 1024, 1);

    logits_kernel<<<gatt, blk, smem_logits>>>(qp, kp, embK, weights);
    softmax_kernel<<<65536, blk>>>(weights);
    av_kernel<<<gatt, blk, smem_av>>>(weights, vp, embV, xp);

    gemm_nt<<<gproj, blk>>>(xp, Wo, bo, outPtr, 4096, 1024, 1024, 0);
}